// round 12
// baseline (speedup 1.0000x reference)
#include <cuda_runtime.h>
#include <cuda_bf16.h>
#include <math.h>

// ---------------------------------------------------------------------------
// Problem constants
// ---------------------------------------------------------------------------
#define BATCH     2048
#define SDIM      64
#define ADIM      16
#define HID       256
#define TDIM      32
#define TSTEPS    100
#define CAT       112            // ADIM + TDIM + SDIM
#define RPC       16             // rows per CTA
#define NRP       8              // row-pairs per CTA
#define NCTA      (BATCH / RPC)  // 128
#define NTHR      512            // 64 col-group threads x 8 k-splits
#define GSTR      18             // ull per 2-col group (16 data + 2 pad)

typedef unsigned long long ull;

// padded layout: value (col c, row-pair rp) at (c>>1)*GSTR + (c&1)*8 + rp
__device__ __forceinline__ int lay(int c, int rp) {
    return (c >> 1) * GSTR + (c & 1) * 8 + rp;
}

// ---------------------------------------------------------------------------
// Precomputed tables
// ---------------------------------------------------------------------------
__device__ float g_temb[TSTEPS * TDIM];
__device__ float g_srac[TSTEPS];
__device__ float g_sracm1[TSTEPS];
__device__ float g_c1[TSTEPS];
__device__ float g_c2[TSTEPS];
__device__ float g_sigma[TSTEPS];

// ---------------------------------------------------------------------------
// f32x2 helpers
// ---------------------------------------------------------------------------
__device__ __forceinline__ ull pack2(float lo, float hi) {
    ull r; asm("mov.b64 %0, {%1, %2};" : "=l"(r) : "f"(lo), "f"(hi)); return r;
}
__device__ __forceinline__ void unpack2(ull v, float& lo, float& hi) {
    asm("mov.b64 {%0, %1}, %2;" : "=f"(lo), "=f"(hi) : "l"(v));
}
__device__ __forceinline__ void fma2(ull& d, ull a, ull b) {
    asm("fma.rn.f32x2 %0, %1, %2, %0;" : "+l"(d) : "l"(a), "l"(b));
}
__device__ __forceinline__ ull add2(ull a, ull b) {
    ull r; asm("add.rn.f32x2 %0, %1, %2;" : "=l"(r) : "l"(a), "l"(b)); return r;
}

// ---------------------------------------------------------------------------
// Fast exact-algebra mish: tanh(softplus(x)) = v/(v+2), v = u^2+2u, u = e^x
// ---------------------------------------------------------------------------
__device__ __forceinline__ float mishf(float x) {
    const float LOG2E = 1.4426950408889634f;
    float xc = fminf(x, 40.0f);
    float u;
    asm("ex2.approx.f32 %0, %1;" : "=f"(u) : "f"(xc * LOG2E));
    float v = fmaf(u, u, u + u);
    float r;
    asm("rcp.approx.f32 %0, %1;" : "=f"(r) : "f"(v + 2.0f));
    return x * v * r;
}

// ---------------------------------------------------------------------------
// Prolog: VP schedule in f64 + per-timestep time-MLP (batch-invariant).
// ---------------------------------------------------------------------------
__global__ void __launch_bounds__(256) prolog_kernel(
    const float* __restrict__ tW1, const float* __restrict__ tb1,
    const float* __restrict__ tW2, const float* __restrict__ tb2)
{
    const int tid = threadIdx.x;
    const int i   = blockIdx.x;

    if (i == 0 && tid == 0) {
        const double T = (double)TSTEPS, bmax = 10.0, bmin = 0.1;
        double ac = 1.0;
        for (int idx = 0; idx < TSTEPS; ++idx) {
            double t      = (double)(idx + 1);
            double alpha  = exp(-bmin / T - 0.5 * (bmax - bmin) * (2.0 * t - 1.0) / (T * T));
            double beta   = 1.0 - alpha;
            double acp    = ac;
            ac            = ac * alpha;
            g_srac[idx]   = (float)sqrt(1.0 / ac);
            g_sracm1[idx] = (float)sqrt(1.0 / ac - 1.0);
            g_c1[idx]     = (float)(beta * sqrt(acp) / (1.0 - ac));
            g_c2[idx]     = (float)((1.0 - acp) * sqrt(alpha) / (1.0 - ac));
            double pv     = beta * (1.0 - acp) / (1.0 - ac);
            if (pv < 1e-20) pv = 1e-20;
            g_sigma[idx]  = (float)exp(0.5 * log(pv));
        }
    }

    __shared__ float emb[TDIM];
    __shared__ float hid[HID];

    if (tid < TDIM) {
        int   j    = tid & 15;
        float freq = expf((float)j * (-logf(10000.0f) / 15.0f));
        float ang  = (float)i * freq;
        emb[tid]   = (tid < 16) ? sinf(ang) : cosf(ang);
    }
    __syncthreads();
    {
        float a = tb1[tid];
#pragma unroll
        for (int j = 0; j < TDIM; ++j)
            a = fmaf(emb[j], tW1[j * HID + tid], a);
        float sp = fmaxf(a, 0.0f) + log1pf(expf(-fabsf(a)));
        hid[tid] = a * tanhf(sp);
    }
    __syncthreads();
    if (tid < TDIM) {
        float a = tb2[tid];
#pragma unroll 8
        for (int h = 0; h < HID; ++h)
            a = fmaf(hid[h], tW2[h * TDIM + tid], a);
        g_temb[i * TDIM + tid] = a;
    }
}

// ---------------------------------------------------------------------------
// Dense layer 256-out, thread tile = 8 row-pairs x 4 cols, k-split 8.
// cols = {cg, cg+64, cg+128, cg+192} so each broadcast activation load feeds
// 64 FFMA2 (2x R11) -> L1 wavefronts drop below the FFMA2-pipe floor.
// Weights: 4 x LDG.32 per k (coalesced, 1 wf each).
// Reduction: 8 partials folded into 2 buffers over 4 short stages
// ({0,1}->store, {2,3},{4,5},{6,7}->add), then combine+mish spread pass.
// ---------------------------------------------------------------------------
template <int K, bool INPLACE>
__device__ __forceinline__ void dense8ks(
    const ull* __restrict__ in,
    const float* __restrict__ W,
    const float* __restrict__ b,
    ull* __restrict__ out,
    ull* __restrict__ red,
    int cg, int ks, int tid)
{
    ull acc[NRP][4];
    if (ks == 0) {
#pragma unroll
        for (int j = 0; j < 4; ++j) {
            const float bv = b[cg + 64 * j];
            const ull bb = pack2(bv, bv);
#pragma unroll
            for (int rp = 0; rp < NRP; ++rp) acc[rp][j] = bb;
        }
    } else {
#pragma unroll
        for (int j = 0; j < 4; ++j)
#pragma unroll
            for (int rp = 0; rp < NRP; ++rp) acc[rp][j] = 0;
    }

    const int kn = K / 8;              // 14 (K=112) or 32 (K=256); even
    const int kb = ks * kn;            // even
    const ull*   ip = in + (kb >> 1) * GSTR;
    const float* wp = W + kb * HID + cg;

#pragma unroll 2
    for (int kk = 0; kk < kn; kk += 2) {
        // even k of the pair
        {
            const ulonglong2 a01 = *(const ulonglong2*)(ip + 0);
            const ulonglong2 a23 = *(const ulonglong2*)(ip + 2);
            const ulonglong2 a45 = *(const ulonglong2*)(ip + 4);
            const ulonglong2 a67 = *(const ulonglong2*)(ip + 6);
            const float f0 = wp[0], f1 = wp[64], f2 = wp[128], f3 = wp[192];
            const ull w0 = pack2(f0, f0), w1 = pack2(f1, f1);
            const ull w2 = pack2(f2, f2), w3 = pack2(f3, f3);
            fma2(acc[0][0], a01.x, w0); fma2(acc[0][1], a01.x, w1);
            fma2(acc[0][2], a01.x, w2); fma2(acc[0][3], a01.x, w3);
            fma2(acc[1][0], a01.y, w0); fma2(acc[1][1], a01.y, w1);
            fma2(acc[1][2], a01.y, w2); fma2(acc[1][3], a01.y, w3);
            fma2(acc[2][0], a23.x, w0); fma2(acc[2][1], a23.x, w1);
            fma2(acc[2][2], a23.x, w2); fma2(acc[2][3], a23.x, w3);
            fma2(acc[3][0], a23.y, w0); fma2(acc[3][1], a23.y, w1);
            fma2(acc[3][2], a23.y, w2); fma2(acc[3][3], a23.y, w3);
            fma2(acc[4][0], a45.x, w0); fma2(acc[4][1], a45.x, w1);
            fma2(acc[4][2], a45.x, w2); fma2(acc[4][3], a45.x, w3);
            fma2(acc[5][0], a45.y, w0); fma2(acc[5][1], a45.y, w1);
            fma2(acc[5][2], a45.y, w2); fma2(acc[5][3], a45.y, w3);
            fma2(acc[6][0], a67.x, w0); fma2(acc[6][1], a67.x, w1);
            fma2(acc[6][2], a67.x, w2); fma2(acc[6][3], a67.x, w3);
            fma2(acc[7][0], a67.y, w0); fma2(acc[7][1], a67.y, w1);
            fma2(acc[7][2], a67.y, w2); fma2(acc[7][3], a67.y, w3);
        }
        // odd k of the pair
        {
            const ulonglong2 a01 = *(const ulonglong2*)(ip + 8);
            const ulonglong2 a23 = *(const ulonglong2*)(ip + 10);
            const ulonglong2 a45 = *(const ulonglong2*)(ip + 12);
            const ulonglong2 a67 = *(const ulonglong2*)(ip + 14);
            const float* wq = wp + HID;
            const float f0 = wq[0], f1 = wq[64], f2 = wq[128], f3 = wq[192];
            const ull w0 = pack2(f0, f0), w1 = pack2(f1, f1);
            const ull w2 = pack2(f2, f2), w3 = pack2(f3, f3);
            fma2(acc[0][0], a01.x, w0); fma2(acc[0][1], a01.x, w1);
            fma2(acc[0][2], a01.x, w2); fma2(acc[0][3], a01.x, w3);
            fma2(acc[1][0], a01.y, w0); fma2(acc[1][1], a01.y, w1);
            fma2(acc[1][2], a01.y, w2); fma2(acc[1][3], a01.y, w3);
            fma2(acc[2][0], a23.x, w0); fma2(acc[2][1], a23.x, w1);
            fma2(acc[2][2], a23.x, w2); fma2(acc[2][3], a23.x, w3);
            fma2(acc[3][0], a23.y, w0); fma2(acc[3][1], a23.y, w1);
            fma2(acc[3][2], a23.y, w2); fma2(acc[3][3], a23.y, w3);
            fma2(acc[4][0], a45.x, w0); fma2(acc[4][1], a45.x, w1);
            fma2(acc[4][2], a45.x, w2); fma2(acc[4][3], a45.x, w3);
            fma2(acc[5][0], a45.y, w0); fma2(acc[5][1], a45.y, w1);
            fma2(acc[5][2], a45.y, w2); fma2(acc[5][3], a45.y, w3);
            fma2(acc[6][0], a67.x, w0); fma2(acc[6][1], a67.x, w1);
            fma2(acc[6][2], a67.x, w2); fma2(acc[6][3], a67.x, w3);
            fma2(acc[7][0], a67.y, w0); fma2(acc[7][1], a67.y, w1);
            fma2(acc[7][2], a67.y, w2); fma2(acc[7][3], a67.y, w3);
        }
        ip += GSTR;
        wp += 2 * HID;
    }

    if (INPLACE) __syncthreads();          // all reads of `in` complete

    // fold 8 partials into 2 buffers over 4 stages
    const int g0 = (cg >> 1);
    const int hh = (cg & 1) * 8;

    // stage 1: ks0 -> out (bias already folded), ks1 -> red
    if (ks < 2) {
        ull* bufb = (ks == 0 ? out : red);
#pragma unroll
        for (int j = 0; j < 4; ++j) {
            ull* o = bufb + (g0 + 32 * j) * GSTR + hh;
            *(ulonglong2*)(o + 0) = make_ulonglong2(acc[0][j], acc[1][j]);
            *(ulonglong2*)(o + 2) = make_ulonglong2(acc[2][j], acc[3][j]);
            *(ulonglong2*)(o + 4) = make_ulonglong2(acc[4][j], acc[5][j]);
            *(ulonglong2*)(o + 6) = make_ulonglong2(acc[6][j], acc[7][j]);
        }
    }
    __syncthreads();

#pragma unroll
    for (int st = 1; st < 4; ++st) {
        if ((ks >> 1) == st) {
            ull* bufb = ((ks & 1) == 0 ? out : red);
#pragma unroll
            for (int j = 0; j < 4; ++j) {
                ull* o = bufb + (g0 + 32 * j) * GSTR + hh;
#pragma unroll
                for (int rp = 0; rp < NRP; rp += 2) {
                    ulonglong2 v = *(ulonglong2*)(o + rp);
                    v.x = add2(v.x, acc[rp][j]);
                    v.y = add2(v.y, acc[rp + 1][j]);
                    *(ulonglong2*)(o + rp) = v;
                }
            }
        }
        __syncthreads();
    }

    // combine + mish spread pass: data ull d = tid*4..+3, padded address
    {
        const int d0   = tid * 4;
        const int base = (d0 >> 4) * GSTR + (d0 & 15);
        ulonglong2* ph = (ulonglong2*)(out + base);
        const ulonglong2* pr = (const ulonglong2*)(red + base);
#pragma unroll
        for (int j = 0; j < 2; ++j) {
            ulonglong2 h = ph[j], r = pr[j];
            float l0, h0, l1, h1;
            unpack2(add2(h.x, r.x), l0, h0);
            unpack2(add2(h.y, r.y), l1, h1);
            ph[j] = make_ulonglong2(pack2(mishf(l0), mishf(h0)),
                                    pack2(mishf(l1), mishf(h1)));
        }
    }
    __syncthreads();
}

// ---------------------------------------------------------------------------
// Fused sampler: CTA owns 16 rows for all 100 steps. 512 threads.
// ---------------------------------------------------------------------------
__global__ void __launch_bounds__(NTHR, 1) sampler_kernel(
    const float* __restrict__ state,
    const float* __restrict__ x_init,
    const float* __restrict__ noise,
    const float* __restrict__ W1, const float* __restrict__ b1,
    const float* __restrict__ W2, const float* __restrict__ b2,
    const float* __restrict__ W3, const float* __restrict__ b3,
    const float* __restrict__ W4, const float* __restrict__ b4,
    float* __restrict__ out)
{
    __shared__ __align__(16) ull a0[(CAT / 2) * GSTR];   //  7.9 KB layer-1 input
    __shared__ __align__(16) ull hbuf[(HID / 2) * GSTR]; // 18.0 KB layers 1-3
    __shared__ __align__(16) ull red[(HID / 2) * GSTR];  // 18.0 KB partials
    // L4 partials (512 ull) alias `red` — dead after the L3 combine pass.
    ull* red4 = red;

    const int tid  = threadIdx.x;
    const int cg   = tid & 63;       // col group 0..63 (cols cg+64j)
    const int ks   = tid >> 6;       // k-eighth 0..7
    const int row0 = blockIdx.x * RPC;

    // ---- one-time fills (padded, row-pair packed) ----
    if (tid < 128) {                 // x: 16 feats x 8 rp
        int f = tid >> 3, rp = tid & 7;
        a0[lay(f, rp)] = pack2(x_init[(row0 + 2 * rp)     * ADIM + f],
                               x_init[(row0 + 2 * rp + 1) * ADIM + f]);
    }
    {                                // state: 64 feats x 8 rp = 512
        int f = tid >> 3, rp = tid & 7;
        a0[lay(ADIM + TDIM + f, rp)] =
            pack2(state[(row0 + 2 * rp)     * SDIM + f],
                  state[(row0 + 2 * rp + 1) * SDIM + f]);
    }

    for (int s = 0; s < TSTEPS; ++s) {
        const int i = TSTEPS - 1 - s;

        if (tid < 256) {             // temb: 32 feats x 8 rp (row-invariant)
            int f = tid >> 3, rp = tid & 7;
            float t = g_temb[i * TDIM + f];
            a0[lay(ADIM + f, rp)] = pack2(t, t);
        }
        __syncthreads();

        dense8ks<CAT, false>(a0,   W1, b1, hbuf, red, cg, ks, tid);
        dense8ks<HID, true >(hbuf, W2, b2, hbuf, red, cg, ks, tid);
        dense8ks<HID, true >(hbuf, W3, b3, hbuf, red, cg, ks, tid);

        // ---- layer 4 (256 -> 16): thread = (k-quarter, rp, c) ----
        {
            const int c  = tid & 15;
            const int rp = (tid >> 4) & 7;
            const int k4 = tid >> 7;        // 0..3
            ull acc = 0;
            const int kb = k4 * 64;
#pragma unroll 8
            for (int kk = 0; kk < 64; ++kk) {
                const int k = kb + kk;
                const float w = W4[k * ADIM + c];
                fma2(acc, hbuf[lay(k, rp)], pack2(w, w));
            }
            red4[(rp * ADIM + c) * 4 + k4] = acc;
        }
        __syncthreads();

        // ---- reduce + posterior (128 threads: rp, c) ----
        if (tid < 128) {
            const int rp = tid >> 4, c = tid & 15;
            const ull* r = red4 + (rp * ADIM + c) * 4;
            ull e = add2(add2(r[0], r[1]), add2(r[2], r[3]));
            float e0, e1; unpack2(e, e0, e1);
            const float bb = b4[c];
            e0 += bb; e1 += bb;

            float x0, x1; unpack2(a0[lay(c, rp)], x0, x1);
            const float sr = g_srac[i], srm = g_sracm1[i];
            const float c1 = g_c1[i],   c2  = g_c2[i];

            float r0 = fminf(fmaxf(sr * x0 - srm * e0, -1.0f), 1.0f);
            float r1 = fminf(fmaxf(sr * x1 - srm * e1, -1.0f), 1.0f);
            float m0 = c1 * r0 + c2 * x0;
            float m1 = c1 * r1 + c2 * x1;

            if (i > 0) {
                const float sg = g_sigma[i];
                const float* nz = noise + (size_t)s * BATCH * ADIM;
                float n0 = nz[(row0 + 2 * rp)     * ADIM + c];
                float n1 = nz[(row0 + 2 * rp + 1) * ADIM + c];
                a0[lay(c, rp)] = pack2(fmaf(sg, n0, m0), fmaf(sg, n1, m1));
            } else {
                out[(row0 + 2 * rp)     * ADIM + c] = fminf(fmaxf(m0, -1.0f), 1.0f);
                out[(row0 + 2 * rp + 1) * ADIM + c] = fminf(fmaxf(m1, -1.0f), 1.0f);
            }
        }
        __syncthreads();
    }
}

// ---------------------------------------------------------------------------
// kernel_launch
// ---------------------------------------------------------------------------
extern "C" void kernel_launch(void* const* d_in, const int* in_sizes, int n_in,
                              void* d_out, int out_size)
{
    const float* state  = (const float*)d_in[0];
    const float* x_init = (const float*)d_in[1];
    const float* noise  = (const float*)d_in[2];
    const float* tW1    = (const float*)d_in[3];
    const float* tb1    = (const float*)d_in[4];
    const float* tW2    = (const float*)d_in[5];
    const float* tb2    = (const float*)d_in[6];
    const float* W1     = (const float*)d_in[7];
    const float* b1     = (const float*)d_in[8];
    const float* W2     = (const float*)d_in[9];
    const float* b2     = (const float*)d_in[10];
    const float* W3     = (const float*)d_in[11];
    const float* b3     = (const float*)d_in[12];
    const float* W4     = (const float*)d_in[13];
    const float* b4     = (const float*)d_in[14];
    float* out          = (float*)d_out;

    prolog_kernel<<<TSTEPS, 256>>>(tW1, tb1, tW2, tb2);
    sampler_kernel<<<NCTA, NTHR>>>(state, x_init, noise,
                                   W1, b1, W2, b2, W3, b3, W4, b4, out);
}

// round 13
// speedup vs baseline: 1.1584x; 1.1584x over previous
#include <cuda_runtime.h>
#include <cuda_bf16.h>
#include <math.h>

// ---------------------------------------------------------------------------
// Problem constants
// ---------------------------------------------------------------------------
#define BATCH     2048
#define SDIM      64
#define ADIM      16
#define HID       256
#define TDIM      32
#define TSTEPS    100
#define CAT       112            // ADIM + TDIM + SDIM
#define RPC       16             // rows per CTA
#define NRP       8              // row-pairs per CTA
#define NCTA      (BATCH / RPC)  // 128
#define NTHR      512            // 64 cg x 2 row-halves x 4 k-splits
#define GSTR      18             // ull per 2-col group (16 data + 2 pad)

typedef unsigned long long ull;

// padded layout: value (col c, row-pair rp) at (c>>1)*GSTR + (c&1)*8 + rp
__device__ __forceinline__ int lay(int c, int rp) {
    return (c >> 1) * GSTR + (c & 1) * 8 + rp;
}

// ---------------------------------------------------------------------------
// Precomputed tables
// ---------------------------------------------------------------------------
__device__ float g_temb[TSTEPS * TDIM];
__device__ float g_srac[TSTEPS];
__device__ float g_sracm1[TSTEPS];
__device__ float g_c1[TSTEPS];
__device__ float g_c2[TSTEPS];
__device__ float g_sigma[TSTEPS];

// ---------------------------------------------------------------------------
// f32x2 helpers
// ---------------------------------------------------------------------------
__device__ __forceinline__ ull pack2(float lo, float hi) {
    ull r; asm("mov.b64 %0, {%1, %2};" : "=l"(r) : "f"(lo), "f"(hi)); return r;
}
__device__ __forceinline__ void unpack2(ull v, float& lo, float& hi) {
    asm("mov.b64 {%0, %1}, %2;" : "=f"(lo), "=f"(hi) : "l"(v));
}
__device__ __forceinline__ void fma2(ull& d, ull a, ull b) {
    asm("fma.rn.f32x2 %0, %1, %2, %0;" : "+l"(d) : "l"(a), "l"(b));
}
__device__ __forceinline__ ull add2(ull a, ull b) {
    ull r; asm("add.rn.f32x2 %0, %1, %2;" : "=l"(r) : "l"(a), "l"(b)); return r;
}

// ---------------------------------------------------------------------------
// Fast exact-algebra mish: tanh(softplus(x)) = v/(v+2), v = u^2+2u, u = e^x
// ---------------------------------------------------------------------------
__device__ __forceinline__ float mishf(float x) {
    const float LOG2E = 1.4426950408889634f;
    float xc = fminf(x, 40.0f);
    float u;
    asm("ex2.approx.f32 %0, %1;" : "=f"(u) : "f"(xc * LOG2E));
    float v = fmaf(u, u, u + u);
    float r;
    asm("rcp.approx.f32 %0, %1;" : "=f"(r) : "f"(v + 2.0f));
    return x * v * r;
}

// ---------------------------------------------------------------------------
// Prolog: VP schedule in f64 + per-timestep time-MLP (batch-invariant).
// ---------------------------------------------------------------------------
__global__ void __launch_bounds__(256) prolog_kernel(
    const float* __restrict__ tW1, const float* __restrict__ tb1,
    const float* __restrict__ tW2, const float* __restrict__ tb2)
{
    const int tid = threadIdx.x;
    const int i   = blockIdx.x;

    if (i == 0 && tid == 0) {
        const double T = (double)TSTEPS, bmax = 10.0, bmin = 0.1;
        double ac = 1.0;
        for (int idx = 0; idx < TSTEPS; ++idx) {
            double t      = (double)(idx + 1);
            double alpha  = exp(-bmin / T - 0.5 * (bmax - bmin) * (2.0 * t - 1.0) / (T * T));
            double beta   = 1.0 - alpha;
            double acp    = ac;
            ac            = ac * alpha;
            g_srac[idx]   = (float)sqrt(1.0 / ac);
            g_sracm1[idx] = (float)sqrt(1.0 / ac - 1.0);
            g_c1[idx]     = (float)(beta * sqrt(acp) / (1.0 - ac));
            g_c2[idx]     = (float)((1.0 - acp) * sqrt(alpha) / (1.0 - ac));
            double pv     = beta * (1.0 - acp) / (1.0 - ac);
            if (pv < 1e-20) pv = 1e-20;
            g_sigma[idx]  = (float)exp(0.5 * log(pv));
        }
    }

    __shared__ float emb[TDIM];
    __shared__ float hid[HID];

    if (tid < TDIM) {
        int   j    = tid & 15;
        float freq = expf((float)j * (-logf(10000.0f) / 15.0f));
        float ang  = (float)i * freq;
        emb[tid]   = (tid < 16) ? sinf(ang) : cosf(ang);
    }
    __syncthreads();
    {
        float a = tb1[tid];
#pragma unroll
        for (int j = 0; j < TDIM; ++j)
            a = fmaf(emb[j], tW1[j * HID + tid], a);
        float sp = fmaxf(a, 0.0f) + log1pf(expf(-fabsf(a)));
        hid[tid] = a * tanhf(sp);
    }
    __syncthreads();
    if (tid < TDIM) {
        float a = tb2[tid];
#pragma unroll 8
        for (int h = 0; h < HID; ++h)
            a = fmaf(hid[h], tW2[h * TDIM + tid], a);
        g_temb[i * TDIM + tid] = a;
    }
}

// ---------------------------------------------------------------------------
// Dense layer 256-out, thread tile = 4 row-pairs x 4 cols, k-split 4.
// Thread = (ks, rh, cg): cols {2cg, 2cg+1, 2cg+128, 2cg+129}, rows
// rp = 4rh..4rh+3. Per k: 2 LDS.128 (broadcast within warp: lanes share
// rh/ks) + 2 LDG.64 + 4 packs + 16 FFMA2 -> L1 per FMA halved vs the
// 8rp x 2c tile, acc down to 32 regs, reduction volume same as R11
// (8K ull, 2 buffers): ks{0,1}->{out,red} store (rh halves disjoint),
// ks{2,3} add, then combine+mish spread pass.
// ---------------------------------------------------------------------------
template <int K, bool INPLACE>
__device__ __forceinline__ void dense44(
    const ull* __restrict__ in,
    const float* __restrict__ W,
    const float* __restrict__ b,
    ull* __restrict__ out,
    ull* __restrict__ red,
    int cg, int rh, int ks, int tid)
{
    const int c0 = 2 * cg;           // pair A cols c0, c0+1
    const int c1 = c0 + 128;         // pair B cols c1, c1+1

    ull acc[4][4];                   // [rp][col: c0, c0+1, c1, c1+1]
    if (ks == 0) {
        const ull bA0 = pack2(b[c0], b[c0]);
        const ull bA1 = pack2(b[c0 + 1], b[c0 + 1]);
        const ull bB0 = pack2(b[c1], b[c1]);
        const ull bB1 = pack2(b[c1 + 1], b[c1 + 1]);
#pragma unroll
        for (int r = 0; r < 4; ++r) {
            acc[r][0] = bA0; acc[r][1] = bA1; acc[r][2] = bB0; acc[r][3] = bB1;
        }
    } else {
#pragma unroll
        for (int r = 0; r < 4; ++r)
#pragma unroll
            for (int j = 0; j < 4; ++j) acc[r][j] = 0;
    }

    const int kn = K / 4;            // 28 (K=112) or 64 (K=256); even
    const int kb = ks * kn;          // even
    const ull*   ip  = in + (kb >> 1) * GSTR + 4 * rh;
    const float* wpA = W + kb * HID + c0;
    const float* wpB = wpA + 128;

#pragma unroll 4
    for (int kk = 0; kk < kn; kk += 2) {
        // even k of the pair
        {
            const ulonglong2 a01 = *(const ulonglong2*)(ip + 0);
            const ulonglong2 a23 = *(const ulonglong2*)(ip + 2);
            const float2 wA = *(const float2*)wpA;
            const float2 wB = *(const float2*)wpB;
            const ull w0 = pack2(wA.x, wA.x), w1 = pack2(wA.y, wA.y);
            const ull w2 = pack2(wB.x, wB.x), w3 = pack2(wB.y, wB.y);
            fma2(acc[0][0], a01.x, w0); fma2(acc[0][1], a01.x, w1);
            fma2(acc[0][2], a01.x, w2); fma2(acc[0][3], a01.x, w3);
            fma2(acc[1][0], a01.y, w0); fma2(acc[1][1], a01.y, w1);
            fma2(acc[1][2], a01.y, w2); fma2(acc[1][3], a01.y, w3);
            fma2(acc[2][0], a23.x, w0); fma2(acc[2][1], a23.x, w1);
            fma2(acc[2][2], a23.x, w2); fma2(acc[2][3], a23.x, w3);
            fma2(acc[3][0], a23.y, w0); fma2(acc[3][1], a23.y, w1);
            fma2(acc[3][2], a23.y, w2); fma2(acc[3][3], a23.y, w3);
        }
        // odd k of the pair
        {
            const ulonglong2 a01 = *(const ulonglong2*)(ip + 8);
            const ulonglong2 a23 = *(const ulonglong2*)(ip + 10);
            const float2 wA = *(const float2*)(wpA + HID);
            const float2 wB = *(const float2*)(wpB + HID);
            const ull w0 = pack2(wA.x, wA.x), w1 = pack2(wA.y, wA.y);
            const ull w2 = pack2(wB.x, wB.x), w3 = pack2(wB.y, wB.y);
            fma2(acc[0][0], a01.x, w0); fma2(acc[0][1], a01.x, w1);
            fma2(acc[0][2], a01.x, w2); fma2(acc[0][3], a01.x, w3);
            fma2(acc[1][0], a01.y, w0); fma2(acc[1][1], a01.y, w1);
            fma2(acc[1][2], a01.y, w2); fma2(acc[1][3], a01.y, w3);
            fma2(acc[2][0], a23.x, w0); fma2(acc[2][1], a23.x, w1);
            fma2(acc[2][2], a23.x, w2); fma2(acc[2][3], a23.x, w3);
            fma2(acc[3][0], a23.y, w0); fma2(acc[3][1], a23.y, w1);
            fma2(acc[3][2], a23.y, w2); fma2(acc[3][3], a23.y, w3);
        }
        ip  += GSTR;
        wpA += 2 * HID;
        wpB += 2 * HID;
    }

    if (INPLACE) __syncthreads();          // all reads of `in` complete

    // stage 1: ks0 -> out (bias folded), ks1 -> red; rh halves disjoint rows
    if (ks < 2) {
        ull* buf = (ks == 0 ? out : red);
        ull* oA = buf + cg * GSTR + 4 * rh;         // col pair A, group cg
        ull* oB = buf + (cg + 64) * GSTR + 4 * rh;  // col pair B, group cg+64
        *(ulonglong2*)(oA + 0)  = make_ulonglong2(acc[0][0], acc[1][0]);
        *(ulonglong2*)(oA + 2)  = make_ulonglong2(acc[2][0], acc[3][0]);
        *(ulonglong2*)(oA + 8)  = make_ulonglong2(acc[0][1], acc[1][1]);
        *(ulonglong2*)(oA + 10) = make_ulonglong2(acc[2][1], acc[3][1]);
        *(ulonglong2*)(oB + 0)  = make_ulonglong2(acc[0][2], acc[1][2]);
        *(ulonglong2*)(oB + 2)  = make_ulonglong2(acc[2][2], acc[3][2]);
        *(ulonglong2*)(oB + 8)  = make_ulonglong2(acc[0][3], acc[1][3]);
        *(ulonglong2*)(oB + 10) = make_ulonglong2(acc[2][3], acc[3][3]);
    }
    __syncthreads();

    // stage 2: ks2 += out, ks3 += red (disjoint buffers & rows)
    if (ks >= 2) {
        ull* buf = (ks == 2 ? out : red);
        ull* oA = buf + cg * GSTR + 4 * rh;
        ull* oB = buf + (cg + 64) * GSTR + 4 * rh;
#pragma unroll
        for (int cc = 0; cc < 2; ++cc) {
            ull* o = (cc == 0 ? oA : oB);
            const int j0 = cc * 2;
            ulonglong2 v0 = *(ulonglong2*)(o + 0);
            v0.x = add2(v0.x, acc[0][j0]); v0.y = add2(v0.y, acc[1][j0]);
            *(ulonglong2*)(o + 0) = v0;
            ulonglong2 v1 = *(ulonglong2*)(o + 2);
            v1.x = add2(v1.x, acc[2][j0]); v1.y = add2(v1.y, acc[3][j0]);
            *(ulonglong2*)(o + 2) = v1;
            ulonglong2 v2 = *(ulonglong2*)(o + 8);
            v2.x = add2(v2.x, acc[0][j0 + 1]); v2.y = add2(v2.y, acc[1][j0 + 1]);
            *(ulonglong2*)(o + 8) = v2;
            ulonglong2 v3 = *(ulonglong2*)(o + 10);
            v3.x = add2(v3.x, acc[2][j0 + 1]); v3.y = add2(v3.y, acc[3][j0 + 1]);
            *(ulonglong2*)(o + 10) = v3;
        }
    }
    __syncthreads();

    // combine + mish spread pass: data ull d = tid*4..+3, padded address
    {
        const int d0   = tid * 4;
        const int base = (d0 >> 4) * GSTR + (d0 & 15);
        ulonglong2* ph = (ulonglong2*)(out + base);
        const ulonglong2* pr = (const ulonglong2*)(red + base);
#pragma unroll
        for (int j = 0; j < 2; ++j) {
            ulonglong2 h = ph[j], r = pr[j];
            float l0, h0, l1, h1;
            unpack2(add2(h.x, r.x), l0, h0);
            unpack2(add2(h.y, r.y), l1, h1);
            ph[j] = make_ulonglong2(pack2(mishf(l0), mishf(h0)),
                                    pack2(mishf(l1), mishf(h1)));
        }
    }
    __syncthreads();
}

// ---------------------------------------------------------------------------
// Fused sampler: CTA owns 16 rows for all 100 steps. 512 threads.
// ---------------------------------------------------------------------------
__global__ void __launch_bounds__(NTHR, 1) sampler_kernel(
    const float* __restrict__ state,
    const float* __restrict__ x_init,
    const float* __restrict__ noise,
    const float* __restrict__ W1, const float* __restrict__ b1,
    const float* __restrict__ W2, const float* __restrict__ b2,
    const float* __restrict__ W3, const float* __restrict__ b3,
    const float* __restrict__ W4, const float* __restrict__ b4,
    float* __restrict__ out)
{
    __shared__ __align__(16) ull a0[(CAT / 2) * GSTR];   //  7.9 KB layer-1 input
    __shared__ __align__(16) ull hbuf[(HID / 2) * GSTR]; // 18.0 KB layers 1-3
    __shared__ __align__(16) ull red[(HID / 2) * GSTR];  // 18.0 KB partials
    // L4 partials (512 ull) alias `red` — dead after the L3 combine pass.
    ull* red4 = red;

    const int tid  = threadIdx.x;
    const int cg   = tid & 63;          // col group 0..63
    const int rh   = (tid >> 6) & 1;    // row half 0..1
    const int ks   = tid >> 7;          // k-quarter 0..3
    const int row0 = blockIdx.x * RPC;

    // ---- one-time fills (padded, row-pair packed) ----
    if (tid < 128) {                 // x: 16 feats x 8 rp
        int f = tid >> 3, rp = tid & 7;
        a0[lay(f, rp)] = pack2(x_init[(row0 + 2 * rp)     * ADIM + f],
                               x_init[(row0 + 2 * rp + 1) * ADIM + f]);
    }
    {                                // state: 64 feats x 8 rp = 512
        int f = tid >> 3, rp = tid & 7;
        a0[lay(ADIM + TDIM + f, rp)] =
            pack2(state[(row0 + 2 * rp)     * SDIM + f],
                  state[(row0 + 2 * rp + 1) * SDIM + f]);
    }

    for (int s = 0; s < TSTEPS; ++s) {
        const int i = TSTEPS - 1 - s;

        if (tid < 256) {             // temb: 32 feats x 8 rp (row-invariant)
            int f = tid >> 3, rp = tid & 7;
            float t = g_temb[i * TDIM + f];
            a0[lay(ADIM + f, rp)] = pack2(t, t);
        }
        __syncthreads();

        dense44<CAT, false>(a0,   W1, b1, hbuf, red, cg, rh, ks, tid);
        dense44<HID, true >(hbuf, W2, b2, hbuf, red, cg, rh, ks, tid);
        dense44<HID, true >(hbuf, W3, b3, hbuf, red, cg, rh, ks, tid);

        // ---- layer 4 (256 -> 16): thread = (k-quarter, rp, c) ----
        {
            const int c  = tid & 15;
            const int rp = (tid >> 4) & 7;
            const int k4 = tid >> 7;        // 0..3
            ull acc = 0;
            const int kb = k4 * 64;
#pragma unroll 8
            for (int kk = 0; kk < 64; ++kk) {
                const int k = kb + kk;
                const float w = W4[k * ADIM + c];
                fma2(acc, hbuf[lay(k, rp)], pack2(w, w));
            }
            red4[(rp * ADIM + c) * 4 + k4] = acc;
        }
        __syncthreads();

        // ---- reduce + posterior (128 threads: rp, c) ----
        if (tid < 128) {
            const int rp = tid >> 4, c = tid & 15;
            const ull* r = red4 + (rp * ADIM + c) * 4;
            ull e = add2(add2(r[0], r[1]), add2(r[2], r[3]));
            float e0, e1; unpack2(e, e0, e1);
            const float bb = b4[c];
            e0 += bb; e1 += bb;

            float x0, x1; unpack2(a0[lay(c, rp)], x0, x1);
            const float sr = g_srac[i], srm = g_sracm1[i];
            const float c1 = g_c1[i],   c2  = g_c2[i];

            float r0 = fminf(fmaxf(sr * x0 - srm * e0, -1.0f), 1.0f);
            float r1 = fminf(fmaxf(sr * x1 - srm * e1, -1.0f), 1.0f);
            float m0 = c1 * r0 + c2 * x0;
            float m1 = c1 * r1 + c2 * x1;

            if (i > 0) {
                const float sg = g_sigma[i];
                const float* nz = noise + (size_t)s * BATCH * ADIM;
                float n0 = nz[(row0 + 2 * rp)     * ADIM + c];
                float n1 = nz[(row0 + 2 * rp + 1) * ADIM + c];
                a0[lay(c, rp)] = pack2(fmaf(sg, n0, m0), fmaf(sg, n1, m1));
            } else {
                out[(row0 + 2 * rp)     * ADIM + c] = fminf(fmaxf(m0, -1.0f), 1.0f);
                out[(row0 + 2 * rp + 1) * ADIM + c] = fminf(fmaxf(m1, -1.0f), 1.0f);
            }
        }
        __syncthreads();
    }
}

// ---------------------------------------------------------------------------
// kernel_launch
// ---------------------------------------------------------------------------
extern "C" void kernel_launch(void* const* d_in, const int* in_sizes, int n_in,
                              void* d_out, int out_size)
{
    const float* state  = (const float*)d_in[0];
    const float* x_init = (const float*)d_in[1];
    const float* noise  = (const float*)d_in[2];
    const float* tW1    = (const float*)d_in[3];
    const float* tb1    = (const float*)d_in[4];
    const float* tW2    = (const float*)d_in[5];
    const float* tb2    = (const float*)d_in[6];
    const float* W1     = (const float*)d_in[7];
    const float* b1     = (const float*)d_in[8];
    const float* W2     = (const float*)d_in[9];
    const float* b2     = (const float*)d_in[10];
    const float* W3     = (const float*)d_in[11];
    const float* b3     = (const float*)d_in[12];
    const float* W4     = (const float*)d_in[13];
    const float* b4     = (const float*)d_in[14];
    float* out          = (float*)d_out;

    prolog_kernel<<<TSTEPS, 256>>>(tW1, tb1, tW2, tb2);
    sampler_kernel<<<NCTA, NTHR>>>(state, x_init, noise,
                                   W1, b1, W2, b2, W3, b3, W4, b4, out);
}